// round 14
// baseline (speedup 1.0000x reference)
#include <cuda_runtime.h>
#include <cuda_fp16.h>
#include <math.h>
#include <cstdint>

#define BB 512
#define HH 2048
#define EE 2048
#define TT 256
#define NG 8192    // 4*H, permuted: n' = hc*4 + gate (i,f,g,o)

// ------------------------------------------------------------------ state
// g_h / g_w stored PRE-SWIZZLED in 16KB tiles (128 rows x 64 k, swz128),
// tile index = (rowblock * 32 + kchunk). Bulk-copy loads them linearly.
__device__ __align__(128) __half g_h[2][BB * HH];
__device__ __align__(128) float  g_c[BB * HH];
__device__ __align__(128) __half g_w[NG * HH];
__device__ __align__(128) float  g_bsum[NG];
__device__ __align__(128) float  g_wih0[NG];
__device__ __align__(128) float  g_wih1[NG];

// ------------------------------------------------------------------ helpers
#define LDSM4(r, a) \
    asm volatile("ldmatrix.sync.aligned.m8n8.x4.shared.b16 {%0,%1,%2,%3}, [%4];" \
        : "=r"((r)[0]), "=r"((r)[1]), "=r"((r)[2]), "=r"((r)[3]) : "r"(a))

#define MBAR_INIT(b, c)   asm volatile("mbarrier.init.shared.b64 [%0], %1;" :: "r"(b), "r"(c) : "memory")
#define MBAR_EXPECT_TX(b, n) asm volatile("mbarrier.arrive.expect_tx.shared.b64 _, [%0], %1;" :: "r"(b), "r"(n) : "memory")
#define MBAR_ARRIVE(b)    asm volatile("mbarrier.arrive.shared.b64 _, [%0];" :: "r"(b) : "memory")
#define FENCE_ASYNC()     asm volatile("fence.proxy.async.shared::cta;" ::: "memory")

#define BULK_G2S(dst, src, bytes, mbar) \
    asm volatile("cp.async.bulk.shared::cta.global.mbarrier::complete_tx::bytes [%0], [%1], %2, [%3];" \
        :: "r"(dst), "l"(src), "r"(bytes), "r"(mbar) : "memory")

#define MBAR_WAIT(bar, ph) do {                                                   \
    uint32_t _b = (bar), _p = (ph), _d;                                           \
    asm volatile("{\n\t.reg .pred p;\n\t"                                         \
        "mbarrier.try_wait.parity.acquire.cta.shared::cta.b64 p, [%1], %2;\n\t"   \
        "selp.b32 %0, 1, 0, p;\n\t}" : "=r"(_d) : "r"(_b), "r"(_p) : "memory");   \
    if (!_d) {                                                                    \
        asm volatile("{\n\t.reg .pred P1;\n\t"                                    \
            "W%=:\n\tmbarrier.try_wait.parity.acquire.cta.shared::cta.b64 P1, [%0], %1, 0x989680;\n\t" \
            "@P1 bra.uni D%=;\n\tbra.uni W%=;\n\tD%=:\n\t}"                       \
            :: "r"(_b), "r"(_p) : "memory");                                      \
    }                                                                             \
} while (0)

__device__ __forceinline__ uint32_t smem_u32(const void* p) {
    uint32_t a;
    asm("{ .reg .u64 t; cvta.to.shared.u64 t, %1; cvt.u32.u64 %0, t; }" : "=r"(a) : "l"(p));
    return a;
}

__device__ __forceinline__ void mma16816(float* d, const uint32_t* a, const uint32_t* b) {
    asm volatile(
        "mma.sync.aligned.m16n8k16.row.col.f32.f16.f16.f32 "
        "{%0,%1,%2,%3}, {%4,%5,%6,%7}, {%8,%9}, {%0,%1,%2,%3};"
        : "+f"(d[0]), "+f"(d[1]), "+f"(d[2]), "+f"(d[3])
        : "r"(a[0]), "r"(a[1]), "r"(a[2]), "r"(a[3]), "r"(b[0]), "r"(b[1]));
}

// fast HW tanh (sm_75+); sigmoid via tanh identity: sigm(x) = 0.5*tanh(x/2)+0.5
__device__ __forceinline__ float tanh_fast(float x) {
    float y;
    asm("tanh.approx.f32 %0, %1;" : "=f"(y) : "f"(x));
    return y;
}
__device__ __forceinline__ float sigm_fast(float x) {
    return fmaf(tanh_fast(0.5f * x), 0.5f, 0.5f);
}
__device__ __forceinline__ float sigm_acc(float x) { return 1.0f / (1.0f + __expf(-x)); }

// element offset (in halves) within a 16KB tile for (row 0..127, k 0..63)
__device__ __forceinline__ uint32_t tile_off(int row, int k) {
    int c8 = k >> 3;
    return (uint32_t)(row * 64 + ((((c8) ^ (row & 7)) & 7) << 3) + (k & 7));
}

// ------------------------------------------------------------------ prep
__global__ void prep_w_kernel(const float* __restrict__ W_hh) {
    int np = blockIdx.x;                 // 0..NG-1 (gate-interleaved row)
    int g = np & 3, hc = np >> 2;
    const float* src = W_hh + (size_t)(g * HH + hc) * HH;
    int nt = np >> 7, row = np & 127;
#pragma unroll
    for (int j = 0; j < HH / 256; j++) {
        int k = threadIdx.x + j * 256;
        size_t idx = (size_t)(nt * 32 + (k >> 6)) * 8192 + tile_off(row, k & 63);
        g_w[idx] = __float2half_rn(src[k]);
    }
}

__global__ void prep_misc_kernel(const float* __restrict__ b_ih, const float* __restrict__ b_hh,
                                 const float* __restrict__ W_ih) {
    int np = blockIdx.x * 256 + threadIdx.x;
    int g = np & 3, hc = np >> 2;
    int j = g * HH + hc;
    g_bsum[np] = b_ih[j] + b_hh[j];
    g_wih0[np] = W_ih[2 * j + 0];
    g_wih1[np] = W_ih[2 * j + 1];
}

__global__ void zero_out_kernel(float* __restrict__ out) {
    int i = blockIdx.x * 256 + threadIdx.x;
    if (i < BB * TT * 3) out[i] = 0.0f;
}

__global__ void stop_final_kernel(float* __restrict__ out, const float* __restrict__ b_stop) {
    int i = blockIdx.x * 256 + threadIdx.x;
    if (i < BB * TT) {
        float v = out[BB * TT * 2 + i];
        out[BB * TT * 2 + i] = sigm_acc(v + b_stop[0]);
    }
}

// ------------------------------------------------------------------ h0 (fp32 SIMT, one-time)
#define KC 16
__global__ __launch_bounds__(256, 2)
void h0_kernel(const float* __restrict__ emb, const float* __restrict__ W,
               const float* __restrict__ bias) {
    __shared__ float As[KC][64];
    __shared__ float Bs[KC][64];
    int tid = threadIdx.x;
    int m0 = blockIdx.y * 64, n0 = blockIdx.x * 64;
    int lrow = tid >> 2, lk4 = (tid & 3) * 4;
    int tx_m = tid >> 4, tx_n = tid & 15;

    float acc[4][4];
#pragma unroll
    for (int i = 0; i < 4; i++)
#pragma unroll
        for (int j = 0; j < 4; j++) acc[i][j] = 0.0f;

    for (int k0 = 0; k0 < EE; k0 += KC) {
        float4 av = *(const float4*)&emb[(m0 + lrow) * EE + k0 + lk4];
        float4 bv = *(const float4*)&W[(n0 + lrow) * EE + k0 + lk4];
        __syncthreads();
        As[lk4 + 0][lrow] = av.x; As[lk4 + 1][lrow] = av.y;
        As[lk4 + 2][lrow] = av.z; As[lk4 + 3][lrow] = av.w;
        Bs[lk4 + 0][lrow] = bv.x; Bs[lk4 + 1][lrow] = bv.y;
        Bs[lk4 + 2][lrow] = bv.z; Bs[lk4 + 3][lrow] = bv.w;
        __syncthreads();
#pragma unroll
        for (int kk = 0; kk < KC; kk++) {
            float a[4], b[4];
            *(float4*)a = *(float4*)&As[kk][tx_m * 4];
            *(float4*)b = *(float4*)&Bs[kk][tx_n * 4];
#pragma unroll
            for (int mi = 0; mi < 4; mi++)
#pragma unroll
                for (int ni = 0; ni < 4; ni++) acc[mi][ni] += a[mi] * b[ni];
        }
    }
#pragma unroll
    for (int mi = 0; mi < 4; mi++) {
        int m = m0 + tx_m * 4 + mi;
#pragma unroll
        for (int ni = 0; ni < 4; ni++) {
            int n = n0 + tx_n * 4 + ni;
            float h = acc[mi][ni] + bias[n];
            size_t idx = (size_t)((m >> 7) * 32 + (n >> 6)) * 8192 + tile_off(m & 127, n & 63);
            g_h[0][idx] = __float2half_rn(h);
        }
    }
}

// ------------------------------------------------------------------ main LSTM step
// CTA tile: 128 M x 128 N, 256 threads = 8 warps (2 m x 4 n of 64x32).
// Grid (64, 4) = 256 CTAs, 2 CTAs/SM. BKC=64, 3-stage bulk-copy pipeline.
// Epilogue split across lane pairs: even lane -> row r, odd lane -> row r+8.
#define NCHUNK 32        // 2048 / 64
#define A_OFF    0
#define B_OFF    16384
#define STAGE_BYTES 32768
#define XS_OFF   0       // 128*2 floats
#define SRED_OFF 1024    // 128*4 floats
#define WH_OFF   3072    // 3*32 floats -> ends 3456
#define BAR_OFF  3520    // 3 full + 3 empty mbarriers (8B each)
#define STAGE0   4096
#define SMEM_TOTAL (STAGE0 + 3 * STAGE_BYTES)

__global__ __launch_bounds__(256, 2)
void lstm_step_mma(float* __restrict__ out, int t,
                   const float* __restrict__ W_out, const float* __restrict__ W_stop,
                   const float* __restrict__ b_out) {
    extern __shared__ char smem[];
    float* x_s  = (float*)(smem + XS_OFF);     // [128][2]
    float* sred = (float*)(smem + SRED_OFF);   // [128][4]
    float* w_s0 = (float*)(smem + WH_OFF);     // [32]
    float* w_s1 = w_s0 + 32;
    float* w_ss = w_s0 + 64;
    int tid = threadIdx.x;
    int wid = tid >> 5, lane = tid & 31;
    int g = lane >> 2, tig = lane & 3;
    int wm = wid & 1, wn = wid >> 1;            // 2 m-warps x 4 n-warps
    int n0 = blockIdx.x * 128, m0 = blockIdx.y * 128;
    int src = t & 1, dst = src ^ 1;
    uint32_t sbase = smem_u32(smem + STAGE0);
    uint32_t fullb = smem_u32(smem + BAR_OFF);          // full[0..2]
    uint32_t emptb = fullb + 24;                        // empty[0..2]

    // pre-swizzled tile pointers (16KB tiles, 8192 halves)
    const __half* atiles = g_h[src] + (size_t)(blockIdx.y * 32) * 8192;
    const __half* btiles = g_w + (size_t)(blockIdx.x * 32) * 8192;

    // mbarrier init (per launch)
    if (tid == 0) {
#pragma unroll
        for (int s = 0; s < 3; s++) {
            MBAR_INIT(fullb + s * 8, 1);
            MBAR_INIT(emptb + s * 8, 8);    // one arrive per warp
        }
        FENCE_ASYNC();
    }

    // ldmatrix lane mapping: A 4 m-frags (64 rows), B 2 frag-pairs (32 cols)
    int arow[4];
#pragma unroll
    for (int mi = 0; mi < 4; mi++) arow[mi] = wm * 64 + mi * 16 + (lane & 15);
    int abit = lane >> 4;
    int brow[2];
#pragma unroll
    for (int nip = 0; nip < 2; nip++)
        brow[nip] = wn * 32 + nip * 16 + ((lane >> 4) << 3) + (lane & 7);
    int bbit = (lane >> 3) & 1;

    uint32_t abase[4], asw[4], bbase[2], bsw[2];
#pragma unroll
    for (int mi = 0; mi < 4; mi++) { abase[mi] = arow[mi] * 128; asw[mi] = arow[mi] & 7; }
#pragma unroll
    for (int nip = 0; nip < 2; nip++) { bbase[nip] = brow[nip] * 128; bsw[nip] = brow[nip] & 7; }

    // preload: prev coords, head weights, zero reduction buffer
    if (tid < 128) {
        float x0 = 0.0f, x1 = 0.0f;
        if (t > 0) {
            x0 = out[((m0 + tid) * TT + t - 1) * 2 + 0];
            x1 = out[((m0 + tid) * TT + t - 1) * 2 + 1];
        }
        x_s[tid * 2 + 0] = x0;
        x_s[tid * 2 + 1] = x1;
        sred[tid * 4 + 0] = 0.0f;
        sred[tid * 4 + 1] = 0.0f;
        sred[tid * 4 + 2] = 0.0f;
    }
    if (tid < 32) {
        int hc = (n0 >> 2) + tid;
        w_s0[tid] = W_out[hc];
        w_s1[tid] = W_out[HH + hc];
        w_ss[tid] = W_stop[hc];
    }
    __syncthreads();    // mbarrier init + preload visible before any TMA / use

    // prologue: chunks 0,1
    if (tid == 0) {
#pragma unroll
        for (int c = 0; c < 2; c++) {
            uint32_t st = sbase + c * STAGE_BYTES;
            MBAR_EXPECT_TX(fullb + c * 8, (uint32_t)STAGE_BYTES);
            BULK_G2S(st + A_OFF, atiles + (size_t)c * 8192, 16384u, fullb + c * 8);
            BULK_G2S(st + B_OFF, btiles + (size_t)c * 8192, 16384u, fullb + c * 8);
        }
    }

    float acc[4][4][4];
#pragma unroll
    for (int mi = 0; mi < 4; mi++)
#pragma unroll
        for (int ni = 0; ni < 4; ni++)
#pragma unroll
            for (int j = 0; j < 4; j++) acc[mi][ni][j] = 0.0f;

    for (int c = 0; c < NCHUNK; c++) {
        int s = c % 3;
        // producer: refill stage (c+2)%3 with chunk c+2 (tid0 only)
        if (tid == 0 && c + 2 < NCHUNK) {
            int q = c + 2, s2 = q % 3;
            if (q >= 3) MBAR_WAIT(emptb + s2 * 8, (q / 3 - 1) & 1);
            uint32_t st = sbase + s2 * STAGE_BYTES;
            MBAR_EXPECT_TX(fullb + s2 * 8, (uint32_t)STAGE_BYTES);
            BULK_G2S(st + A_OFF, atiles + (size_t)q * 8192, 16384u, fullb + s2 * 8);
            BULK_G2S(st + B_OFF, btiles + (size_t)q * 8192, 16384u, fullb + s2 * 8);
        }
        // consumer: wait data for chunk c
        MBAR_WAIT(fullb + s * 8, (c / 3) & 1);

        uint32_t stage = sbase + s * STAGE_BYTES;
#pragma unroll
        for (int kk = 0; kk < 4; kk++) {
            uint32_t ah[4][4];
#pragma unroll
            for (int mi = 0; mi < 4; mi++) {
                int cc = kk * 2 + abit;
                uint32_t ao = abase[mi] + (((cc ^ asw[mi]) & 7) << 4);
                LDSM4(ah[mi], stage + A_OFF + ao);
            }
#pragma unroll
            for (int nip = 0; nip < 2; nip++) {
                int cc = kk * 2 + bbit;
                uint32_t bo = bbase[nip] + (((cc ^ bsw[nip]) & 7) << 4);
                uint32_t bh[4];
                LDSM4(bh, stage + B_OFF + bo);
#pragma unroll
                for (int ni2 = 0; ni2 < 2; ni2++)
#pragma unroll
                    for (int mi = 0; mi < 4; mi++)
                        mma16816(acc[mi][nip * 2 + ni2], ah[mi], bh + ni2 * 2);
            }
        }
        // this warp done reading stage s
        if (lane == 0) MBAR_ARRIVE(emptb + s * 8);
    }

    // ------------------------------ fused LSTM epilogue + head partials
    // Lane pair split: even lane handles row r0, odd lane row r0+8.
    // Gate columns (i,f,g,o) = cols (c0,c1,c2,c3); even lane owns c0,c1;
    // odd lane owns c2,c3; shfl_xor(1) exchanges the other half.
    __half* hdst = g_h[dst];
    int odd = tig & 1;
#pragma unroll
    for (int mi = 0; mi < 4; mi++) {
        int rl = wm * 64 + mi * 16 + g + odd * 8;     // this lane's row
        int m = m0 + rl;
        float x0 = x_s[rl * 2 + 0], x1 = x_s[rl * 2 + 1];
        float hs0 = 0.0f, hs1 = 0.0f, hs2 = 0.0f;
#pragma unroll
        for (int ni = 0; ni < 4; ni++) {
            float o0 = acc[mi][ni][0], o1 = acc[mi][ni][1];
            float o2 = acc[mi][ni][2], o3 = acc[mi][ni][3];
            float p0 = __shfl_xor_sync(0xFFFFFFFFu, o0, 1);
            float p1 = __shfl_xor_sync(0xFFFFFFFFu, o1, 1);
            float p2 = __shfl_xor_sync(0xFFFFFFFFu, o2, 1);
            float p3 = __shfl_xor_sync(0xFFFFFFFFu, o3, 1);
            // even lane row r: i=o0 f=o1 g=p0 o=p1 ; odd lane row r+8: i=p2 f=p3 g=o2 o=o3
            float vi = odd ? p2 : o0;
            float vf = odd ? p3 : o1;
            float vg = odd ? o2 : p0;
            float vo = odd ? o3 : p1;
            int col = wn * 32 + ni * 8 + 2 * (tig & 2);   // gate-i column (mult of 4), same for pair
            int np = n0 + col;
            float4 bs = *(const float4*)&g_bsum[np];
            float4 wa = *(const float4*)&g_wih0[np];
            float4 wb = *(const float4*)&g_wih1[np];
            int hc = np >> 2;
            float pi = vi + bs.x + x0 * wa.x + x1 * wb.x;
            float pf = vf + bs.y + x0 * wa.y + x1 * wb.y;
            float pg = vg + bs.z + x0 * wa.z + x1 * wb.z;
            float po = vo + bs.w + x0 * wa.w + x1 * wb.w;
            float cp = (t == 0) ? 0.0f : g_c[m * HH + hc];
            float cn = sigm_fast(pf) * cp + sigm_fast(pi) * tanh_fast(pg);
            g_c[m * HH + hc] = cn;
            float h = sigm_fast(po) * tanh_fast(cn);
            size_t htile = (size_t)((m0 >> 7) * 32 + (hc >> 6)) * 8192;
            hdst[htile + tile_off(rl, hc & 63)] = __float2half_rn(h);
            float w0v = w_s0[col >> 2], w1v = w_s1[col >> 2], wsv = w_ss[col >> 2];
            hs0 += h * w0v;
            hs1 += h * w1v;
            hs2 += h * wsv;
        }
        atomicAdd(&sred[rl * 4 + 0], hs0);
        atomicAdd(&sred[rl * 4 + 1], hs1);
        atomicAdd(&sred[rl * 4 + 2], hs2);
    }
    __syncthreads();
    if (tid < 128) {
        int m = m0 + tid;
        float b0 = 0.0f, b1 = 0.0f;
        if (blockIdx.x == 0) { b0 = b_out[0]; b1 = b_out[1]; }
        atomicAdd(&out[(m * TT + t) * 2 + 0], sred[tid * 4 + 0] + b0);
        atomicAdd(&out[(m * TT + t) * 2 + 1], sred[tid * 4 + 1] + b1);
        atomicAdd(&out[BB * TT * 2 + m * TT + t], sred[tid * 4 + 2]);
    }
}

// ------------------------------------------------------------------ launch
extern "C" void kernel_launch(void* const* d_in, const int* in_sizes, int n_in,
                              void* d_out, int out_size) {
    const float* emb     = (const float*)d_in[0];
    const float* W_embed = (const float*)d_in[2];
    const float* b_embed = (const float*)d_in[3];
    const float* W_ih    = (const float*)d_in[4];
    const float* b_ih    = (const float*)d_in[5];
    const float* W_hh    = (const float*)d_in[6];
    const float* b_hh    = (const float*)d_in[7];
    const float* W_out   = (const float*)d_in[8];
    const float* b_out   = (const float*)d_in[9];
    const float* W_stop  = (const float*)d_in[10];
    const float* b_stop  = (const float*)d_in[11];
    float* out = (float*)d_out;

    cudaFuncSetAttribute(lstm_step_mma, cudaFuncAttributeMaxDynamicSharedMemorySize, SMEM_TOTAL);

    zero_out_kernel<<<(BB * TT * 3 + 255) / 256, 256>>>(out);
    prep_w_kernel<<<NG, 256>>>(W_hh);
    prep_misc_kernel<<<NG / 256, 256>>>(b_ih, b_hh, W_ih);
    h0_kernel<<<dim3(HH / 64, BB / 64), 256>>>(emb, W_embed, b_embed);

    for (int t = 0; t < TT; t++) {
        lstm_step_mma<<<dim3(64, 4), 256, SMEM_TOTAL>>>(out, t, W_out, W_stop, b_out);
    }
    stop_final_kernel<<<(BB * TT + 255) / 256, 256>>>(out, b_stop);
}

// round 15
// speedup vs baseline: 1.6814x; 1.6814x over previous
#include <cuda_runtime.h>
#include <cuda_fp16.h>
#include <math.h>
#include <cstdint>

#define BB 512
#define HH 2048
#define EE 2048
#define TT 256
#define NG 8192    // 4*H, permuted: n' = hc*4 + gate (i,f,g,o)

// ------------------------------------------------------------------ state
// g_h / g_w stored PRE-SWIZZLED in 16KB tiles (128 rows x 64 k, swz128),
// tile index = (rowblock * 32 + kchunk). Bulk-copy loads them linearly.
__device__ __align__(128) __half g_h[2][BB * HH];
__device__ __align__(128) float  g_c[BB * HH];
__device__ __align__(128) __half g_w[NG * HH];
__device__ __align__(128) float  g_bsum[NG];
__device__ __align__(128) float  g_wih0[NG];
__device__ __align__(128) float  g_wih1[NG];

// ------------------------------------------------------------------ helpers
#define LDSM4(r, a) \
    asm volatile("ldmatrix.sync.aligned.m8n8.x4.shared.b16 {%0,%1,%2,%3}, [%4];" \
        : "=r"((r)[0]), "=r"((r)[1]), "=r"((r)[2]), "=r"((r)[3]) : "r"(a))

#define MBAR_INIT(b, c)   asm volatile("mbarrier.init.shared.b64 [%0], %1;" :: "r"(b), "r"(c) : "memory")
#define MBAR_EXPECT_TX(b, n) asm volatile("mbarrier.arrive.expect_tx.shared.b64 _, [%0], %1;" :: "r"(b), "r"(n) : "memory")
#define MBAR_ARRIVE(b)    asm volatile("mbarrier.arrive.shared.b64 _, [%0];" :: "r"(b) : "memory")
#define FENCE_ASYNC()     asm volatile("fence.proxy.async.shared::cta;" ::: "memory")

#define BULK_G2S(dst, src, bytes, mbar) \
    asm volatile("cp.async.bulk.shared::cta.global.mbarrier::complete_tx::bytes [%0], [%1], %2, [%3];" \
        :: "r"(dst), "l"(src), "r"(bytes), "r"(mbar) : "memory")

#define MBAR_WAIT(bar, ph) do {                                                   \
    uint32_t _b = (bar), _p = (ph), _d;                                           \
    asm volatile("{\n\t.reg .pred p;\n\t"                                         \
        "mbarrier.try_wait.parity.acquire.cta.shared::cta.b64 p, [%1], %2;\n\t"   \
        "selp.b32 %0, 1, 0, p;\n\t}" : "=r"(_d) : "r"(_b), "r"(_p) : "memory");   \
    if (!_d) {                                                                    \
        asm volatile("{\n\t.reg .pred P1;\n\t"                                    \
            "W%=:\n\tmbarrier.try_wait.parity.acquire.cta.shared::cta.b64 P1, [%0], %1, 0x989680;\n\t" \
            "@P1 bra.uni D%=;\n\tbra.uni W%=;\n\tD%=:\n\t}"                       \
            :: "r"(_b), "r"(_p) : "memory");                                      \
    }                                                                             \
} while (0)

__device__ __forceinline__ uint32_t smem_u32(const void* p) {
    uint32_t a;
    asm("{ .reg .u64 t; cvta.to.shared.u64 t, %1; cvt.u32.u64 %0, t; }" : "=r"(a) : "l"(p));
    return a;
}

__device__ __forceinline__ void mma16816(float* d, const uint32_t* a, const uint32_t* b) {
    asm volatile(
        "mma.sync.aligned.m16n8k16.row.col.f32.f16.f16.f32 "
        "{%0,%1,%2,%3}, {%4,%5,%6,%7}, {%8,%9}, {%0,%1,%2,%3};"
        : "+f"(d[0]), "+f"(d[1]), "+f"(d[2]), "+f"(d[3])
        : "r"(a[0]), "r"(a[1]), "r"(a[2]), "r"(a[3]), "r"(b[0]), "r"(b[1]));
}

// fast HW tanh (sm_75+); sigmoid via tanh identity: sigm(x) = 0.5*tanh(x/2)+0.5
__device__ __forceinline__ float tanh_fast(float x) {
    float y;
    asm("tanh.approx.f32 %0, %1;" : "=f"(y) : "f"(x));
    return y;
}
__device__ __forceinline__ float sigm_fast(float x) {
    return fmaf(tanh_fast(0.5f * x), 0.5f, 0.5f);
}
__device__ __forceinline__ float sigm_acc(float x) { return 1.0f / (1.0f + __expf(-x)); }

// element offset (in halves) within a 16KB tile for (row 0..127, k 0..63)
__device__ __forceinline__ uint32_t tile_off(int row, int k) {
    int c8 = k >> 3;
    return (uint32_t)(row * 64 + ((((c8) ^ (row & 7)) & 7) << 3) + (k & 7));
}

// ------------------------------------------------------------------ prep
__global__ void prep_w_kernel(const float* __restrict__ W_hh) {
    int np = blockIdx.x;                 // 0..NG-1 (gate-interleaved row)
    int g = np & 3, hc = np >> 2;
    const float* src = W_hh + (size_t)(g * HH + hc) * HH;
    int nt = np >> 7, row = np & 127;
#pragma unroll
    for (int j = 0; j < HH / 256; j++) {
        int k = threadIdx.x + j * 256;
        size_t idx = (size_t)(nt * 32 + (k >> 6)) * 8192 + tile_off(row, k & 63);
        g_w[idx] = __float2half_rn(src[k]);
    }
}

__global__ void prep_misc_kernel(const float* __restrict__ b_ih, const float* __restrict__ b_hh,
                                 const float* __restrict__ W_ih) {
    int np = blockIdx.x * 256 + threadIdx.x;
    int g = np & 3, hc = np >> 2;
    int j = g * HH + hc;
    g_bsum[np] = b_ih[j] + b_hh[j];
    g_wih0[np] = W_ih[2 * j + 0];
    g_wih1[np] = W_ih[2 * j + 1];
}

__global__ void zero_out_kernel(float* __restrict__ out) {
    int i = blockIdx.x * 256 + threadIdx.x;
    if (i < BB * TT * 3) out[i] = 0.0f;
}

__global__ void stop_final_kernel(float* __restrict__ out, const float* __restrict__ b_stop) {
    int i = blockIdx.x * 256 + threadIdx.x;
    if (i < BB * TT) {
        float v = out[BB * TT * 2 + i];
        out[BB * TT * 2 + i] = sigm_acc(v + b_stop[0]);
    }
}

// ------------------------------------------------------------------ h0 (fp32 SIMT, one-time)
#define KC 16
__global__ __launch_bounds__(256, 2)
void h0_kernel(const float* __restrict__ emb, const float* __restrict__ W,
               const float* __restrict__ bias) {
    __shared__ float As[KC][64];
    __shared__ float Bs[KC][64];
    int tid = threadIdx.x;
    int m0 = blockIdx.y * 64, n0 = blockIdx.x * 64;
    int lrow = tid >> 2, lk4 = (tid & 3) * 4;
    int tx_m = tid >> 4, tx_n = tid & 15;

    float acc[4][4];
#pragma unroll
    for (int i = 0; i < 4; i++)
#pragma unroll
        for (int j = 0; j < 4; j++) acc[i][j] = 0.0f;

    for (int k0 = 0; k0 < EE; k0 += KC) {
        float4 av = *(const float4*)&emb[(m0 + lrow) * EE + k0 + lk4];
        float4 bv = *(const float4*)&W[(n0 + lrow) * EE + k0 + lk4];
        __syncthreads();
        As[lk4 + 0][lrow] = av.x; As[lk4 + 1][lrow] = av.y;
        As[lk4 + 2][lrow] = av.z; As[lk4 + 3][lrow] = av.w;
        Bs[lk4 + 0][lrow] = bv.x; Bs[lk4 + 1][lrow] = bv.y;
        Bs[lk4 + 2][lrow] = bv.z; Bs[lk4 + 3][lrow] = bv.w;
        __syncthreads();
#pragma unroll
        for (int kk = 0; kk < KC; kk++) {
            float a[4], b[4];
            *(float4*)a = *(float4*)&As[kk][tx_m * 4];
            *(float4*)b = *(float4*)&Bs[kk][tx_n * 4];
#pragma unroll
            for (int mi = 0; mi < 4; mi++)
#pragma unroll
                for (int ni = 0; ni < 4; ni++) acc[mi][ni] += a[mi] * b[ni];
        }
    }
#pragma unroll
    for (int mi = 0; mi < 4; mi++) {
        int m = m0 + tx_m * 4 + mi;
#pragma unroll
        for (int ni = 0; ni < 4; ni++) {
            int n = n0 + tx_n * 4 + ni;
            float h = acc[mi][ni] + bias[n];
            size_t idx = (size_t)((m >> 7) * 32 + (n >> 6)) * 8192 + tile_off(m & 127, n & 63);
            g_h[0][idx] = __float2half_rn(h);
        }
    }
}

// ------------------------------------------------------------------ main LSTM step
// CTA tile: 128 M x 128 N, 256 threads = 8 warps (2 m x 4 n of 64x32).
// Grid (64, 4) = 256 CTAs, 2 CTAs/SM. BKC=64, 3-stage bulk-copy pipeline.
// R13 epilogue (even lanes) + smem-staged params + atomic-free sred.
#define NCHUNK 32        // 2048 / 64
#define A_OFF    0
#define B_OFF    16384
#define STAGE_BYTES 32768
#define XS_OFF   0       // 128*2 floats = 1024B
#define SRED_OFF 1024    // 128*4*3 floats = 6144B -> ends 7168
#define BSP_OFF  7168    // 128 floats
#define WAP_OFF  7680    // 128 floats
#define WBP_OFF  8192    // 128 floats
#define WH_OFF   8704    // 3*32 floats -> ends 9088
#define BAR_OFF  9088    // 6 mbarriers (48B)
#define STAGE0   10240
#define SMEM_TOTAL (STAGE0 + 3 * STAGE_BYTES)

__global__ __launch_bounds__(256, 2)
void lstm_step_mma(float* __restrict__ out, int t,
                   const float* __restrict__ W_out, const float* __restrict__ W_stop,
                   const float* __restrict__ b_out) {
    extern __shared__ char smem[];
    float* x_s  = (float*)(smem + XS_OFF);     // [128][2]
    float* sred = (float*)(smem + SRED_OFF);   // [128][4][3]
    float* bs_s = (float*)(smem + BSP_OFF);    // [128]
    float* wa_s = (float*)(smem + WAP_OFF);    // [128]
    float* wb_s = (float*)(smem + WBP_OFF);    // [128]
    float* w_s0 = (float*)(smem + WH_OFF);     // [32]
    float* w_s1 = w_s0 + 32;
    float* w_ss = w_s0 + 64;
    int tid = threadIdx.x;
    int wid = tid >> 5, lane = tid & 31;
    int g = lane >> 2, tig = lane & 3;
    int wm = wid & 1, wn = wid >> 1;            // 2 m-warps x 4 n-warps
    int n0 = blockIdx.x * 128, m0 = blockIdx.y * 128;
    int src = t & 1, dst = src ^ 1;
    uint32_t sbase = smem_u32(smem + STAGE0);
    uint32_t fullb = smem_u32(smem + BAR_OFF);          // full[0..2]
    uint32_t emptb = fullb + 24;                        // empty[0..2]

    // pre-swizzled tile pointers (16KB tiles, 8192 halves)
    const __half* atiles = g_h[src] + (size_t)(blockIdx.y * 32) * 8192;
    const __half* btiles = g_w + (size_t)(blockIdx.x * 32) * 8192;

    // mbarrier init (per launch)
    if (tid == 0) {
#pragma unroll
        for (int s = 0; s < 3; s++) {
            MBAR_INIT(fullb + s * 8, 1);
            MBAR_INIT(emptb + s * 8, 8);    // one arrive per warp
        }
        FENCE_ASYNC();
    }

    // ldmatrix lane mapping: A 4 m-frags (64 rows), B 2 frag-pairs (32 cols)
    int arow[4];
#pragma unroll
    for (int mi = 0; mi < 4; mi++) arow[mi] = wm * 64 + mi * 16 + (lane & 15);
    int abit = lane >> 4;
    int brow[2];
#pragma unroll
    for (int nip = 0; nip < 2; nip++)
        brow[nip] = wn * 32 + nip * 16 + ((lane >> 4) << 3) + (lane & 7);
    int bbit = (lane >> 3) & 1;

    uint32_t abase[4], asw[4], bbase[2], bsw[2];
#pragma unroll
    for (int mi = 0; mi < 4; mi++) { abase[mi] = arow[mi] * 128; asw[mi] = arow[mi] & 7; }
#pragma unroll
    for (int nip = 0; nip < 2; nip++) { bbase[nip] = brow[nip] * 128; bsw[nip] = brow[nip] & 7; }

    // preload: prev coords, epilogue params, head weights
    if (tid < 128) {
        float x0 = 0.0f, x1 = 0.0f;
        if (t > 0) {
            x0 = out[((m0 + tid) * TT + t - 1) * 2 + 0];
            x1 = out[((m0 + tid) * TT + t - 1) * 2 + 1];
        }
        x_s[tid * 2 + 0] = x0;
        x_s[tid * 2 + 1] = x1;
        bs_s[tid] = g_bsum[n0 + tid];
        wa_s[tid] = g_wih0[n0 + tid];
        wb_s[tid] = g_wih1[n0 + tid];
    }
    if (tid < 32) {
        int hc = (n0 >> 2) + tid;
        w_s0[tid] = W_out[hc];
        w_s1[tid] = W_out[HH + hc];
        w_ss[tid] = W_stop[hc];
    }
    __syncthreads();    // mbarrier init + preload visible before any TMA / use

    // prologue: chunks 0,1
    if (tid == 0) {
#pragma unroll
        for (int c = 0; c < 2; c++) {
            uint32_t st = sbase + c * STAGE_BYTES;
            MBAR_EXPECT_TX(fullb + c * 8, (uint32_t)STAGE_BYTES);
            BULK_G2S(st + A_OFF, atiles + (size_t)c * 8192, 16384u, fullb + c * 8);
            BULK_G2S(st + B_OFF, btiles + (size_t)c * 8192, 16384u, fullb + c * 8);
        }
    }

    float acc[4][4][4];
#pragma unroll
    for (int mi = 0; mi < 4; mi++)
#pragma unroll
        for (int ni = 0; ni < 4; ni++)
#pragma unroll
            for (int j = 0; j < 4; j++) acc[mi][ni][j] = 0.0f;

    for (int c = 0; c < NCHUNK; c++) {
        int s = c % 3;
        // producer: refill stage (c+2)%3 with chunk c+2 (tid0 only)
        if (tid == 0 && c + 2 < NCHUNK) {
            int q = c + 2, s2 = q % 3;
            if (q >= 3) MBAR_WAIT(emptb + s2 * 8, (q / 3 - 1) & 1);
            uint32_t st = sbase + s2 * STAGE_BYTES;
            MBAR_EXPECT_TX(fullb + s2 * 8, (uint32_t)STAGE_BYTES);
            BULK_G2S(st + A_OFF, atiles + (size_t)q * 8192, 16384u, fullb + s2 * 8);
            BULK_G2S(st + B_OFF, btiles + (size_t)q * 8192, 16384u, fullb + s2 * 8);
        }
        // consumer: wait data for chunk c
        MBAR_WAIT(fullb + s * 8, (c / 3) & 1);

        uint32_t stage = sbase + s * STAGE_BYTES;
#pragma unroll
        for (int kk = 0; kk < 4; kk++) {
            uint32_t ah[4][4];
#pragma unroll
            for (int mi = 0; mi < 4; mi++) {
                int cc = kk * 2 + abit;
                uint32_t ao = abase[mi] + (((cc ^ asw[mi]) & 7) << 4);
                LDSM4(ah[mi], stage + A_OFF + ao);
            }
#pragma unroll
            for (int nip = 0; nip < 2; nip++) {
                int cc = kk * 2 + bbit;
                uint32_t bo = bbase[nip] + (((cc ^ bsw[nip]) & 7) << 4);
                uint32_t bh[4];
                LDSM4(bh, stage + B_OFF + bo);
#pragma unroll
                for (int ni2 = 0; ni2 < 2; ni2++)
#pragma unroll
                    for (int mi = 0; mi < 4; mi++)
                        mma16816(acc[mi][nip * 2 + ni2], ah[mi], bh + ni2 * 2);
            }
        }
        // this warp done reading stage s
        if (lane == 0) MBAR_ARRIVE(emptb + s * 8);
    }

    // ------------------------------ fused LSTM epilogue + head partials
    // Even lanes compute (R13 layout); tig0+tig2 partials combined via shfl,
    // tig0 plain-stores its rows' partials to sred[row][wn][3] (no atomics).
    __half* hdst = g_h[dst];
#pragma unroll
    for (int mi = 0; mi < 4; mi++) {
        int r0 = wm * 64 + mi * 16 + g;
        float hs[2][3] = {{0.0f, 0.0f, 0.0f}, {0.0f, 0.0f, 0.0f}};
#pragma unroll
        for (int ni = 0; ni < 4; ni++) {
            float o0 = acc[mi][ni][0], o1 = acc[mi][ni][1];
            float o2 = acc[mi][ni][2], o3 = acc[mi][ni][3];
            float p0 = __shfl_xor_sync(0xFFFFFFFFu, o0, 1);
            float p1 = __shfl_xor_sync(0xFFFFFFFFu, o1, 1);
            float p2 = __shfl_xor_sync(0xFFFFFFFFu, o2, 1);
            float p3 = __shfl_xor_sync(0xFFFFFFFFu, o3, 1);
            if ((tig & 1) == 0) {
                int col = wn * 32 + ni * 8 + 2 * tig;
                float4 bs = *(const float4*)&bs_s[col];
                float4 wa = *(const float4*)&wa_s[col];
                float4 wb = *(const float4*)&wb_s[col];
                int hc = (n0 + col) >> 2;
                int hcl = col >> 2;
                float w0v = w_s0[hcl], w1v = w_s1[hcl], wsv = w_ss[hcl];
                size_t htile = (size_t)((m0 >> 7) * 32 + (hc >> 6)) * 8192;
#pragma unroll
                for (int rr = 0; rr < 2; rr++) {
                    int rl = r0 + rr * 8;
                    int m = m0 + rl;
                    float x0 = x_s[rl * 2 + 0], x1 = x_s[rl * 2 + 1];
                    float vi = rr ? o2 : o0, vf = rr ? o3 : o1;
                    float vg = rr ? p2 : p0, vo = rr ? p3 : p1;
                    float pi = vi + bs.x + x0 * wa.x + x1 * wb.x;
                    float pf = vf + bs.y + x0 * wa.y + x1 * wb.y;
                    float pg = vg + bs.z + x0 * wa.z + x1 * wb.z;
                    float po = vo + bs.w + x0 * wa.w + x1 * wb.w;
                    float cp = (t == 0) ? 0.0f : g_c[m * HH + hc];
                    float cn = sigm_fast(pf) * cp + sigm_fast(pi) * tanh_fast(pg);
                    g_c[m * HH + hc] = cn;
                    float h = sigm_fast(po) * tanh_fast(cn);
                    hdst[htile + tile_off(rl, hc & 63)] = __float2half_rn(h);
                    hs[rr][0] += h * w0v;
                    hs[rr][1] += h * w1v;
                    hs[rr][2] += h * wsv;
                }
            }
        }
        // combine tig0 + tig2 partials, tig0 stores (rows unique per (mi,g,rr))
#pragma unroll
        for (int rr = 0; rr < 2; rr++) {
#pragma unroll
            for (int j = 0; j < 3; j++) {
                float v = hs[rr][j];
                v += __shfl_xor_sync(0xFFFFFFFFu, v, 2);
                if (tig == 0) sred[((r0 + rr * 8) * 4 + wn) * 3 + j] = v;
            }
        }
    }
    __syncthreads();
    if (tid < 128) {
        int m = m0 + tid;
        float s0 = 0.0f, s1 = 0.0f, s2 = 0.0f;
#pragma unroll
        for (int w = 0; w < 4; w++) {
            s0 += sred[(tid * 4 + w) * 3 + 0];
            s1 += sred[(tid * 4 + w) * 3 + 1];
            s2 += sred[(tid * 4 + w) * 3 + 2];
        }
        float b0 = 0.0f, b1 = 0.0f;
        if (blockIdx.x == 0) { b0 = b_out[0]; b1 = b_out[1]; }
        atomicAdd(&out[(m * TT + t) * 2 + 0], s0 + b0);
        atomicAdd(&out[(m * TT + t) * 2 + 1], s1 + b1);
        atomicAdd(&out[BB * TT * 2 + m * TT + t], s2);
    }
}

// ------------------------------------------------------------------ launch
extern "C" void kernel_launch(void* const* d_in, const int* in_sizes, int n_in,
                              void* d_out, int out_size) {
    const float* emb     = (const float*)d_in[0];
    const float* W_embed = (const float*)d_in[2];
    const float* b_embed = (const float*)d_in[3];
    const float* W_ih    = (const float*)d_in[4];
    const float* b_ih    = (const float*)d_in[5];
    const float* W_hh    = (const float*)d_in[6];
    const float* b_hh    = (const float*)d_in[7];
    const float* W_out   = (const float*)d_in[8];
    const float* b_out   = (const float*)d_in[9];
    const float* W_stop  = (const float*)d_in[10];
    const float* b_stop  = (const float*)d_in[11];
    float* out = (float*)d_out;

    cudaFuncSetAttribute(lstm_step_mma, cudaFuncAttributeMaxDynamicSharedMemorySize, SMEM_TOTAL);

    zero_out_kernel<<<(BB * TT * 3 + 255) / 256, 256>>>(out);
    prep_w_kernel<<<NG, 256>>>(W_hh);
    prep_misc_kernel<<<NG / 256, 256>>>(b_ih, b_hh, W_ih);
    h0_kernel<<<dim3(HH / 64, BB / 64), 256>>>(emb, W_embed, b_embed);

    for (int t = 0; t < TT; t++) {
        lstm_step_mma<<<dim3(64, 4), 256, SMEM_TOTAL>>>(out, t, W_out, W_stop, b_out);
    }
    stop_final_kernel<<<(BB * TT + 255) / 256, 256>>>(out, b_stop);
}

// round 16
// speedup vs baseline: 1.7070x; 1.0152x over previous
#include <cuda_runtime.h>
#include <cuda_fp16.h>
#include <math.h>
#include <cstdint>

#define BB 512
#define HH 2048
#define EE 2048
#define TT 256
#define NG 8192    // 4*H, permuted: n' = hc*4 + gate (i,f,g,o)

// ------------------------------------------------------------------ state
// All mma operands stored PRE-SWIZZLED in 16KB tiles (128 rows x 64 k, swz128),
// tile index = (rowblock * 32 + kchunk). Bulk-copy loads them linearly.
__device__ __align__(128) __half g_h[2][BB * HH];
__device__ __align__(128) float  g_c[BB * HH];
__device__ __align__(128) __half g_w[NG * HH];
__device__ __align__(128) __half g_a0[BB * EE];      // emb, fp16 tiles
__device__ __align__(128) __half g_wemb[HH * EE];    // W_embed, fp16 tiles
__device__ __align__(128) float  g_bsum[NG];
__device__ __align__(128) float  g_wih0[NG];
__device__ __align__(128) float  g_wih1[NG];

// ------------------------------------------------------------------ helpers
#define LDSM4(r, a) \
    asm volatile("ldmatrix.sync.aligned.m8n8.x4.shared.b16 {%0,%1,%2,%3}, [%4];" \
        : "=r"((r)[0]), "=r"((r)[1]), "=r"((r)[2]), "=r"((r)[3]) : "r"(a))

#define MBAR_INIT(b, c)   asm volatile("mbarrier.init.shared.b64 [%0], %1;" :: "r"(b), "r"(c) : "memory")
#define MBAR_EXPECT_TX(b, n) asm volatile("mbarrier.arrive.expect_tx.shared.b64 _, [%0], %1;" :: "r"(b), "r"(n) : "memory")
#define MBAR_ARRIVE(b)    asm volatile("mbarrier.arrive.shared.b64 _, [%0];" :: "r"(b) : "memory")
#define FENCE_ASYNC()     asm volatile("fence.proxy.async.shared::cta;" ::: "memory")

#define BULK_G2S(dst, src, bytes, mbar) \
    asm volatile("cp.async.bulk.shared::cta.global.mbarrier::complete_tx::bytes [%0], [%1], %2, [%3];" \
        :: "r"(dst), "l"(src), "r"(bytes), "r"(mbar) : "memory")

#define MBAR_WAIT(bar, ph) do {                                                   \
    uint32_t _b = (bar), _p = (ph), _d;                                           \
    asm volatile("{\n\t.reg .pred p;\n\t"                                         \
        "mbarrier.try_wait.parity.acquire.cta.shared::cta.b64 p, [%1], %2;\n\t"   \
        "selp.b32 %0, 1, 0, p;\n\t}" : "=r"(_d) : "r"(_b), "r"(_p) : "memory");   \
    if (!_d) {                                                                    \
        asm volatile("{\n\t.reg .pred P1;\n\t"                                    \
            "W%=:\n\tmbarrier.try_wait.parity.acquire.cta.shared::cta.b64 P1, [%0], %1, 0x989680;\n\t" \
            "@P1 bra.uni D%=;\n\tbra.uni W%=;\n\tD%=:\n\t}"                       \
            :: "r"(_b), "r"(_p) : "memory");                                      \
    }                                                                             \
} while (0)

__device__ __forceinline__ uint32_t smem_u32(const void* p) {
    uint32_t a;
    asm("{ .reg .u64 t; cvta.to.shared.u64 t, %1; cvt.u32.u64 %0, t; }" : "=r"(a) : "l"(p));
    return a;
}

__device__ __forceinline__ void mma16816(float* d, const uint32_t* a, const uint32_t* b) {
    asm volatile(
        "mma.sync.aligned.m16n8k16.row.col.f32.f16.f16.f32 "
        "{%0,%1,%2,%3}, {%4,%5,%6,%7}, {%8,%9}, {%0,%1,%2,%3};"
        : "+f"(d[0]), "+f"(d[1]), "+f"(d[2]), "+f"(d[3])
        : "r"(a[0]), "r"(a[1]), "r"(a[2]), "r"(a[3]), "r"(b[0]), "r"(b[1]));
}

// fast HW tanh (sm_75+); sigmoid via tanh identity
__device__ __forceinline__ float tanh_fast(float x) {
    float y;
    asm("tanh.approx.f32 %0, %1;" : "=f"(y) : "f"(x));
    return y;
}
__device__ __forceinline__ float sigm_fast(float x) {
    return fmaf(tanh_fast(0.5f * x), 0.5f, 0.5f);
}
__device__ __forceinline__ float sigm_acc(float x) { return 1.0f / (1.0f + __expf(-x)); }

// element offset (in halves) within a 16KB tile for (row 0..127, k 0..63)
__device__ __forceinline__ uint32_t tile_off(int row, int k) {
    int c8 = k >> 3;
    return (uint32_t)(row * 64 + ((((c8) ^ (row & 7)) & 7) << 3) + (k & 7));
}

// ------------------------------------------------------------------ prep
__global__ void prep_w_kernel(const float* __restrict__ W_hh) {
    int np = blockIdx.x;                 // 0..NG-1 (gate-interleaved row)
    int g = np & 3, hc = np >> 2;
    const float* src = W_hh + (size_t)(g * HH + hc) * HH;
    int nt = np >> 7, row = np & 127;
#pragma unroll
    for (int j = 0; j < HH / 256; j++) {
        int k = threadIdx.x + j * 256;
        size_t idx = (size_t)(nt * 32 + (k >> 6)) * 8192 + tile_off(row, k & 63);
        g_w[idx] = __float2half_rn(src[k]);
    }
}

// emb [BB, EE] -> fp16 tiles; W_embed [HH, EE] -> fp16 tiles (no permute)
__global__ void prep_h0_kernel(const float* __restrict__ emb, const float* __restrict__ W_embed) {
    int r = blockIdx.x;                  // 0..(BB+HH-1)
    const float* src;
    __half* dst;
    int row = r & 127, blk = r >> 7;
    if (r < BB) {
        src = emb + (size_t)r * EE;
        dst = g_a0;
    } else {
        int n = r - BB;
        src = W_embed + (size_t)n * EE;
        dst = g_wemb;
        row = n & 127; blk = n >> 7;
    }
#pragma unroll
    for (int j = 0; j < EE / 256; j++) {
        int k = threadIdx.x + j * 256;
        size_t idx = (size_t)(blk * 32 + (k >> 6)) * 8192 + tile_off(row, k & 63);
        dst[idx] = __float2half_rn(src[k]);
    }
}

__global__ void prep_misc_kernel(const float* __restrict__ b_ih, const float* __restrict__ b_hh,
                                 const float* __restrict__ W_ih) {
    int np = blockIdx.x * 256 + threadIdx.x;
    int g = np & 3, hc = np >> 2;
    int j = g * HH + hc;
    g_bsum[np] = b_ih[j] + b_hh[j];
    g_wih0[np] = W_ih[2 * j + 0];
    g_wih1[np] = W_ih[2 * j + 1];
}

__global__ void zero_out_kernel(float* __restrict__ out) {
    int i = blockIdx.x * 256 + threadIdx.x;
    if (i < BB * TT * 3) out[i] = 0.0f;
}

__global__ void stop_final_kernel(float* __restrict__ out, const float* __restrict__ b_stop) {
    int i = blockIdx.x * 256 + threadIdx.x;
    if (i < BB * TT) {
        float v = out[BB * TT * 2 + i];
        out[BB * TT * 2 + i] = sigm_acc(v + b_stop[0]);
    }
}

// ------------------------------------------------------------------ shared tiling constants
#define NCHUNK 32        // 2048 / 64
#define A_OFF    0
#define B_OFF    16384
#define STAGE_BYTES 32768
#define XS_OFF   0       // 128*2 floats = 1024B
#define SRED_OFF 1024    // 128*4*3 floats = 6144B -> ends 7168
#define BSP_OFF  7168    // 128 floats
#define WAP_OFF  7680    // 128 floats
#define WBP_OFF  8192    // 128 floats
#define WH_OFF   8704    // 3*32 floats -> ends 9088
#define BAR_OFF  9088    // 6 mbarriers (48B)
#define STAGE0   10240
#define SMEM_TOTAL (STAGE0 + 3 * STAGE_BYTES)

// ------------------------------------------------------------------ h0 via fp16 mma
// h0 = emb @ W_embed^T + b_embed. Grid (16, 4), 256 threads, same pipeline.
__global__ __launch_bounds__(256, 2)
void h0_mma(const float* __restrict__ b_embed) {
    extern __shared__ char smem[];
    float* bias_s = (float*)(smem + BSP_OFF);   // [128]
    int tid = threadIdx.x;
    int wid = tid >> 5, lane = tid & 31;
    int g = lane >> 2, tig = lane & 3;
    int wm = wid & 1, wn = wid >> 1;
    int n0 = blockIdx.x * 128, m0 = blockIdx.y * 128;
    uint32_t sbase = smem_u32(smem + STAGE0);
    uint32_t fullb = smem_u32(smem + BAR_OFF);
    uint32_t emptb = fullb + 24;

    const __half* atiles = g_a0 + (size_t)(blockIdx.y * 32) * 8192;
    const __half* btiles = g_wemb + (size_t)(blockIdx.x * 32) * 8192;

    // producer-side init + early prologue (thread-local visibility is enough)
    if (tid == 0) {
#pragma unroll
        for (int s = 0; s < 3; s++) {
            MBAR_INIT(fullb + s * 8, 1);
            MBAR_INIT(emptb + s * 8, 8);
        }
        FENCE_ASYNC();
#pragma unroll
        for (int c = 0; c < 2; c++) {
            uint32_t st = sbase + c * STAGE_BYTES;
            MBAR_EXPECT_TX(fullb + c * 8, (uint32_t)STAGE_BYTES);
            BULK_G2S(st + A_OFF, atiles + (size_t)c * 8192, 16384u, fullb + c * 8);
            BULK_G2S(st + B_OFF, btiles + (size_t)c * 8192, 16384u, fullb + c * 8);
        }
    }

    int arow[4];
#pragma unroll
    for (int mi = 0; mi < 4; mi++) arow[mi] = wm * 64 + mi * 16 + (lane & 15);
    int abit = lane >> 4;
    int brow[2];
#pragma unroll
    for (int nip = 0; nip < 2; nip++)
        brow[nip] = wn * 32 + nip * 16 + ((lane >> 4) << 3) + (lane & 7);
    int bbit = (lane >> 3) & 1;

    uint32_t abase[4], asw[4], bbase[2], bsw[2];
#pragma unroll
    for (int mi = 0; mi < 4; mi++) { abase[mi] = arow[mi] * 128; asw[mi] = arow[mi] & 7; }
#pragma unroll
    for (int nip = 0; nip < 2; nip++) { bbase[nip] = brow[nip] * 128; bsw[nip] = brow[nip] & 7; }

    if (tid < 128) bias_s[tid] = b_embed[n0 + tid];
    __syncthreads();    // init + bias visible to all before waits / epilogue

    float acc[4][4][4];
#pragma unroll
    for (int mi = 0; mi < 4; mi++)
#pragma unroll
        for (int ni = 0; ni < 4; ni++)
#pragma unroll
            for (int j = 0; j < 4; j++) acc[mi][ni][j] = 0.0f;

    for (int c = 0; c < NCHUNK; c++) {
        int s = c % 3;
        if (tid == 0 && c + 2 < NCHUNK) {
            int q = c + 2, s2 = q % 3;
            if (q >= 3) MBAR_WAIT(emptb + s2 * 8, (q / 3 - 1) & 1);
            uint32_t st = sbase + s2 * STAGE_BYTES;
            MBAR_EXPECT_TX(fullb + s2 * 8, (uint32_t)STAGE_BYTES);
            BULK_G2S(st + A_OFF, atiles + (size_t)q * 8192, 16384u, fullb + s2 * 8);
            BULK_G2S(st + B_OFF, btiles + (size_t)q * 8192, 16384u, fullb + s2 * 8);
        }
        MBAR_WAIT(fullb + s * 8, (c / 3) & 1);

        uint32_t stage = sbase + s * STAGE_BYTES;
#pragma unroll
        for (int kk = 0; kk < 4; kk++) {
            uint32_t ah[4][4];
#pragma unroll
            for (int mi = 0; mi < 4; mi++) {
                int cc = kk * 2 + abit;
                uint32_t ao = abase[mi] + (((cc ^ asw[mi]) & 7) << 4);
                LDSM4(ah[mi], stage + A_OFF + ao);
            }
#pragma unroll
            for (int nip = 0; nip < 2; nip++) {
                int cc = kk * 2 + bbit;
                uint32_t bo = bbase[nip] + (((cc ^ bsw[nip]) & 7) << 4);
                uint32_t bh[4];
                LDSM4(bh, stage + B_OFF + bo);
#pragma unroll
                for (int ni2 = 0; ni2 < 2; ni2++)
#pragma unroll
                    for (int mi = 0; mi < 4; mi++)
                        mma16816(acc[mi][nip * 2 + ni2], ah[mi], bh + ni2 * 2);
            }
        }
        if (lane == 0) MBAR_ARRIVE(emptb + s * 8);
    }

    // epilogue: h0 = acc + bias -> g_h[0] swizzled tiles (n = hc)
    __half* hdst = g_h[0];
#pragma unroll
    for (int mi = 0; mi < 4; mi++) {
        int r0 = wm * 64 + mi * 16 + g;
#pragma unroll
        for (int ni = 0; ni < 4; ni++) {
            int col = wn * 32 + ni * 8 + 2 * tig;   // this lane's 2 columns
            int n = n0 + col;
            float b0 = bias_s[col], b1 = bias_s[col + 1];
            size_t tile0 = (size_t)((m0 >> 7) * 32 + (n >> 6)) * 8192;
            size_t tile1 = (size_t)((m0 >> 7) * 32 + ((n + 1) >> 6)) * 8192;
#pragma unroll
            for (int rr = 0; rr < 2; rr++) {
                int rl = r0 + rr * 8;
                float v0 = acc[mi][ni][rr * 2 + 0] + b0;
                float v1 = acc[mi][ni][rr * 2 + 1] + b1;
                hdst[tile0 + tile_off(rl, n & 63)] = __float2half_rn(v0);
                hdst[tile1 + tile_off(rl, (n + 1) & 63)] = __float2half_rn(v1);
            }
        }
    }
}

// ------------------------------------------------------------------ main LSTM step
// CTA tile: 128 M x 128 N, 256 threads = 8 warps (2 m x 4 n of 64x32).
// Grid (64, 4) = 256 CTAs, 2 CTAs/SM. BKC=64, 3-stage bulk-copy pipeline.
__global__ __launch_bounds__(256, 2)
void lstm_step_mma(float* __restrict__ out, int t,
                   const float* __restrict__ W_out, const float* __restrict__ W_stop,
                   const float* __restrict__ b_out) {
    extern __shared__ char smem[];
    float* x_s  = (float*)(smem + XS_OFF);     // [128][2]
    float* sred = (float*)(smem + SRED_OFF);   // [128][4][3]
    float* bs_s = (float*)(smem + BSP_OFF);    // [128]
    float* wa_s = (float*)(smem + WAP_OFF);    // [128]
    float* wb_s = (float*)(smem + WBP_OFF);    // [128]
    float* w_s0 = (float*)(smem + WH_OFF);     // [32]
    float* w_s1 = w_s0 + 32;
    float* w_ss = w_s0 + 64;
    int tid = threadIdx.x;
    int wid = tid >> 5, lane = tid & 31;
    int g = lane >> 2, tig = lane & 3;
    int wm = wid & 1, wn = wid >> 1;            // 2 m-warps x 4 n-warps
    int n0 = blockIdx.x * 128, m0 = blockIdx.y * 128;
    int src = t & 1, dst = src ^ 1;
    uint32_t sbase = smem_u32(smem + STAGE0);
    uint32_t fullb = smem_u32(smem + BAR_OFF);          // full[0..2]
    uint32_t emptb = fullb + 24;                        // empty[0..2]

    const __half* atiles = g_h[src] + (size_t)(blockIdx.y * 32) * 8192;
    const __half* btiles = g_w + (size_t)(blockIdx.x * 32) * 8192;

    // producer-side init + early prologue (before the block barrier)
    if (tid == 0) {
#pragma unroll
        for (int s = 0; s < 3; s++) {
            MBAR_INIT(fullb + s * 8, 1);
            MBAR_INIT(emptb + s * 8, 8);
        }
        FENCE_ASYNC();
#pragma unroll
        for (int c = 0; c < 2; c++) {
            uint32_t st = sbase + c * STAGE_BYTES;
            MBAR_EXPECT_TX(fullb + c * 8, (uint32_t)STAGE_BYTES);
            BULK_G2S(st + A_OFF, atiles + (size_t)c * 8192, 16384u, fullb + c * 8);
            BULK_G2S(st + B_OFF, btiles + (size_t)c * 8192, 16384u, fullb + c * 8);
        }
    }

    // ldmatrix lane mapping
    int arow[4];
#pragma unroll
    for (int mi = 0; mi < 4; mi++) arow[mi] = wm * 64 + mi * 16 + (lane & 15);
    int abit = lane >> 4;
    int brow[2];
#pragma unroll
    for (int nip = 0; nip < 2; nip++)
        brow[nip] = wn * 32 + nip * 16 + ((lane >> 4) << 3) + (lane & 7);
    int bbit = (lane >> 3) & 1;

    uint32_t abase[4], asw[4], bbase[2], bsw[2];
#pragma unroll
    for (int mi = 0; mi < 4; mi++) { abase[mi] = arow[mi] * 128; asw[mi] = arow[mi] & 7; }
#pragma unroll
    for (int nip = 0; nip < 2; nip++) { bbase[nip] = brow[nip] * 128; bsw[nip] = brow[nip] & 7; }

    // preload: prev coords, epilogue params, head weights
    if (tid < 128) {
        float x0 = 0.0f, x1 = 0.0f;
        if (t > 0) {
            x0 = out[((m0 + tid) * TT + t - 1) * 2 + 0];
            x1 = out[((m0 + tid) * TT + t - 1) * 2 + 1];
        }
        x_s[tid * 2 + 0] = x0;
        x_s[tid * 2 + 1] = x1;
        bs_s[tid] = g_bsum[n0 + tid];
        wa_s[tid] = g_wih0[n0 + tid];
        wb_s[tid] = g_wih1[n0 + tid];
    }
    if (tid < 32) {
        int hc = (n0 >> 2) + tid;
        w_s0[tid] = W_out[hc];
        w_s1[tid] = W_out[HH + hc];
        w_ss[tid] = W_stop[hc];
    }
    __syncthreads();    // mbarrier init + preload visible to all

    float acc[4][4][4];
#pragma unroll
    for (int mi = 0; mi < 4; mi++)
#pragma unroll
        for (int ni = 0; ni < 4; ni++)
#pragma unroll
            for (int j = 0; j < 4; j++) acc[mi][ni][j] = 0.0f;

    for (int c = 0; c < NCHUNK; c++) {
        int s = c % 3;
        if (tid == 0 && c + 2 < NCHUNK) {
            int q = c + 2, s2 = q % 3;
            if (q >= 3) MBAR_WAIT(emptb + s2 * 8, (q / 3 - 1) & 1);
            uint32_t st = sbase + s2 * STAGE_BYTES;
            MBAR_EXPECT_TX(fullb + s2 * 8, (uint32_t)STAGE_BYTES);
            BULK_G2S(st + A_OFF, atiles + (size_t)q * 8192, 16384u, fullb + s2 * 8);
            BULK_G2S(st + B_OFF, btiles + (size_t)q * 8192, 16384u, fullb + s2 * 8);
        }
        MBAR_WAIT(fullb + s * 8, (c / 3) & 1);

        uint32_t stage = sbase + s * STAGE_BYTES;
#pragma unroll
        for (int kk = 0; kk < 4; kk++) {
            uint32_t ah[4][4];
#pragma unroll
            for (int mi = 0; mi < 4; mi++) {
                int cc = kk * 2 + abit;
                uint32_t ao = abase[mi] + (((cc ^ asw[mi]) & 7) << 4);
                LDSM4(ah[mi], stage + A_OFF + ao);
            }
#pragma unroll
            for (int nip = 0; nip < 2; nip++) {
                int cc = kk * 2 + bbit;
                uint32_t bo = bbase[nip] + (((cc ^ bsw[nip]) & 7) << 4);
                uint32_t bh[4];
                LDSM4(bh, stage + B_OFF + bo);
#pragma unroll
                for (int ni2 = 0; ni2 < 2; ni2++)
#pragma unroll
                    for (int mi = 0; mi < 4; mi++)
                        mma16816(acc[mi][nip * 2 + ni2], ah[mi], bh + ni2 * 2);
            }
        }
        if (lane == 0) MBAR_ARRIVE(emptb + s * 8);
    }

    // ------------------------------ fused LSTM epilogue + head partials
    __half* hdst = g_h[dst];
#pragma unroll
    for (int mi = 0; mi < 4; mi++) {
        int r0 = wm * 64 + mi * 16 + g;
        float hs[2][3] = {{0.0f, 0.0f, 0.0f}, {0.0f, 0.0f, 0.0f}};
#pragma unroll
        for (int ni = 0; ni < 4; ni++) {
            float o0 = acc[mi][ni][0], o1 = acc[mi][ni][1];
            float o2 = acc[mi][ni][2], o3 = acc[mi][ni][3];
            float p0 = __shfl_xor_sync(0xFFFFFFFFu, o0, 1);
            float p1 = __shfl_xor_sync(0xFFFFFFFFu, o1, 1);
            float p2 = __shfl_xor_sync(0xFFFFFFFFu, o2, 1);
            float p3 = __shfl_xor_sync(0xFFFFFFFFu, o3, 1);
            if ((tig & 1) == 0) {
                int col = wn * 32 + ni * 8 + 2 * tig;
                float4 bs = *(const float4*)&bs_s[col];
                float4 wa = *(const float4*)&wa_s[col];
                float4 wb = *(const float4*)&wb_s[col];
                int hc = (n0 + col) >> 2;
                int hcl = col >> 2;
                float w0v = w_s0[hcl], w1v = w_s1[hcl], wsv = w_ss[hcl];
                size_t htile = (size_t)((m0 >> 7) * 32 + (hc >> 6)) * 8192;
#pragma unroll
                for (int rr = 0; rr < 2; rr++) {
                    int rl = r0 + rr * 8;
                    int m = m0 + rl;
                    float x0 = x_s[rl * 2 + 0], x1 = x_s[rl * 2 + 1];
                    float vi = rr ? o2 : o0, vf = rr ? o3 : o1;
                    float vg = rr ? p2 : p0, vo = rr ? p3 : p1;
                    float pi = vi + bs.x + x0 * wa.x + x1 * wb.x;
                    float pf = vf + bs.y + x0 * wa.y + x1 * wb.y;
                    float pg = vg + bs.z + x0 * wa.z + x1 * wb.z;
                    float po = vo + bs.w + x0 * wa.w + x1 * wb.w;
                    float cp = (t == 0) ? 0.0f : g_c[m * HH + hc];
                    float cn = sigm_fast(pf) * cp + sigm_fast(pi) * tanh_fast(pg);
                    g_c[m * HH + hc] = cn;
                    float h = sigm_fast(po) * tanh_fast(cn);
                    hdst[htile + tile_off(rl, hc & 63)] = __float2half_rn(h);
                    hs[rr][0] += h * w0v;
                    hs[rr][1] += h * w1v;
                    hs[rr][2] += h * wsv;
                }
            }
        }
#pragma unroll
        for (int rr = 0; rr < 2; rr++) {
#pragma unroll
            for (int j = 0; j < 3; j++) {
                float v = hs[rr][j];
                v += __shfl_xor_sync(0xFFFFFFFFu, v, 2);
                if (tig == 0) sred[((r0 + rr * 8) * 4 + wn) * 3 + j] = v;
            }
        }
    }
    __syncthreads();
    if (tid < 128) {
        int m = m0 + tid;
        float s0 = 0.0f, s1 = 0.0f, s2 = 0.0f;
#pragma unroll
        for (int w = 0; w < 4; w++) {
            s0 += sred[(tid * 4 + w) * 3 + 0];
            s1 += sred[(tid * 4 + w) * 3 + 1];
            s2 += sred[(tid * 4 + w) * 3 + 2];
        }
        float b0 = 0.0f, b1 = 0.0f;
        if (blockIdx.x == 0) { b0 = b_out[0]; b1 = b_out[1]; }
        atomicAdd(&out[(m * TT + t) * 2 + 0], s0 + b0);
        atomicAdd(&out[(m * TT + t) * 2 + 1], s1 + b1);
        atomicAdd(&out[BB * TT * 2 + m * TT + t], s2);
    }
}

// ------------------------------------------------------------------ launch
extern "C" void kernel_launch(void* const* d_in, const int* in_sizes, int n_in,
                              void* d_out, int out_size) {
    const float* emb     = (const float*)d_in[0];
    const float* W_embed = (const float*)d_in[2];
    const float* b_embed = (const float*)d_in[3];
    const float* W_ih    = (const float*)d_in[4];
    const float* b_ih    = (const float*)d_in[5];
    const float* W_hh    = (const float*)d_in[6];
    const float* b_hh    = (const float*)d_in[7];
    const float* W_out   = (const float*)d_in[8];
    const float* b_out   = (const float*)d_in[9];
    const float* W_stop  = (const float*)d_in[10];
    const float* b_stop  = (const float*)d_in[11];
    float* out = (float*)d_out;

    cudaFuncSetAttribute(lstm_step_mma, cudaFuncAttributeMaxDynamicSharedMemorySize, SMEM_TOTAL);
    cudaFuncSetAttribute(h0_mma, cudaFuncAttributeMaxDynamicSharedMemorySize, SMEM_TOTAL);

    zero_out_kernel<<<(BB * TT * 3 + 255) / 256, 256>>>(out);
    prep_w_kernel<<<NG, 256>>>(W_hh);
    prep_h0_kernel<<<BB + HH, 256>>>(emb, W_embed);
    prep_misc_kernel<<<NG / 256, 256>>>(b_ih, b_hh, W_ih);
    h0_mma<<<dim3(HH / 128, BB / 128), 256, SMEM_TOTAL>>>(b_embed);

    for (int t = 0; t < TT; t++) {
        lstm_step_mma<<<dim3(64, 4), 256, SMEM_TOTAL>>>(out, t, W_out, W_stop, b_out);
    }
    stop_final_kernel<<<(BB * TT + 255) / 256, 256>>>(out, b_stop);
}